// round 14
// baseline (speedup 1.0000x reference)
#include <cuda_runtime.h>
#include <cuda_bf16.h>
#include <cuda_fp16.h>
#include <math.h>
#include <stdint.h>

#define NC      128       // persistent CTAs
#define TSTEPS  512

// ---------------- scratch (__device__ globals; no runtime allocation) ------
__device__ __half g_xh[(size_t)128 * 512 * 512];     // x fp16  [B][T][512]
__device__ __half g_hf[2][128 * 1024];               // h fp16 (ping-pong)
__device__ unsigned g_bar_count;                     // monotone step counter

// ---------------- SMEM layout (dynamic, bytes) -------------------------------
// ws : Wh fragments fp16: [ks64][gate3][jhalf2][lane32][reg2] u32 = 96KB
// wsi: Wi fragments fp16: [ksx32][gate3][jhalf2][lane32][reg2] u32 = 48KB
// A staging (h): per-PAIR, 3 bufs x (16 rows x 272B)
// X staging (x): per-PAIR, 3 bufs x (16 rows x 144B)
#define WS_OFF     0
#define WSI_OFF    98304
#define A_OFF      147456
#define A_BUF_SZ   4352          // 16 rows * 272B
#define A_PAIR_SZ  13056         // 3 bufs
#define X_OFF      199680
#define X_BUF_SZ   2304          // 16 rows * 144B
#define X_PAIR_SZ  6912          // 3 bufs
#define SMEM_TOTAL 227328

// ---------------- PTX helpers ------------------------------------------------
__device__ __forceinline__ void mma_f16(float* c, const uint32_t* a,
                                        uint32_t b0, uint32_t b1) {
    asm volatile(
        "mma.sync.aligned.m16n8k16.row.col.f32.f16.f16.f32 "
        "{%0,%1,%2,%3}, {%4,%5,%6,%7}, {%8,%9}, {%0,%1,%2,%3};"
        : "+f"(c[0]), "+f"(c[1]), "+f"(c[2]), "+f"(c[3])
        : "r"(a[0]), "r"(a[1]), "r"(a[2]), "r"(a[3]), "r"(b0), "r"(b1));
}

__device__ __forceinline__ void ldmatrix_x4(uint32_t* a, uint32_t addr) {
    asm volatile(
        "ldmatrix.sync.aligned.m8n8.x4.shared.b16 {%0,%1,%2,%3}, [%4];"
        : "=r"(a[0]), "=r"(a[1]), "=r"(a[2]), "=r"(a[3]) : "r"(addr));
}

__device__ __forceinline__ void cp16(uint32_t dst, const void* src) {
    asm volatile("cp.async.cg.shared.global [%0], [%1], 16;"
                 :: "r"(dst), "l"(src) : "memory");
}

// ---------------- fast gate math (ex2/rcp approx) ----------------------------
#define LOG2E 1.4426950408889634f
__device__ __forceinline__ float fexp2a(float x) {
    float r; asm("ex2.approx.f32 %0, %1;" : "=f"(r) : "f"(x)); return r;
}
__device__ __forceinline__ float frcpa(float x) {
    float r; asm("rcp.approx.f32 %0, %1;" : "=f"(r) : "f"(x)); return r;
}
__device__ __forceinline__ float fsigmoid(float x) {
    return frcpa(1.f + fexp2a(-x * LOG2E));
}
__device__ __forceinline__ float ftanh_(float x) {
    return 2.f * frcpa(1.f + fexp2a(-2.f * LOG2E * x)) - 1.f;
}

// ---------------- prep: x -> fp16 --------------------------------------------
__global__ __launch_bounds__(256) void split_x(const float* __restrict__ x)
{
    const size_t i = (size_t)blockIdx.x * 256 + threadIdx.x;
    g_xh[i] = __float2half_rn(x[i]);
}

// ---------------- init: zero h buffer 0 + reset barrier counter -------------
__global__ void init_state()
{
    const int idx = blockIdx.x * 256 + threadIdx.x;   // < 131072
    g_hf[0][idx] = __float2half(0.f);
    if (idx == 0) g_bar_count = 0;
}

// ---------------- monotone-counter grid barrier (acquire-poll) --------------
__device__ __forceinline__ void grid_barrier_step(unsigned target)
{
    __syncthreads();
    if (threadIdx.x == 0) {
        asm volatile("red.release.gpu.global.add.u32 [%0], 1;"
                     :: "l"(&g_bar_count) : "memory");
        unsigned v;
        do {
            asm volatile("ld.acquire.gpu.global.u32 %0, [%1];"
                         : "=r"(v) : "l"(&g_bar_count) : "memory");
        } while (v < target);
    }
    __syncthreads();
}

// ---------------- persistent FUSED GRU: xi production + recurrence -----------
// 128 CTAs x 256 threads. CTA (jg=bid>>1, bhalf=bid&1): j0 = jg*16 (3 gates,
// N=48), batch rows [bhalf*64, +64). Warp: m-tile mw=wid>>1 (16 rows),
// j-half nh=wid&1. Pair (same mw) shares A/X staging (each warp loads half,
// named barrier 1+mw per chunk).
// Per step t: 8 chunks; each chunk does 24 h-mma (K=128 of Wh) AND 12 xi-mma
// (K=64 of Wi, computing xi for step t+1 into registers). xi never touches
// global memory; both mma D fragments land in the consuming thread's coords.
__global__ __launch_bounds__(256, 1)
void gru_fused_persist(const float* __restrict__ Wh, const float* __restrict__ Wi,
                       const float* __restrict__ bi, const float* __restrict__ bh,
                       float* __restrict__ out)
{
    extern __shared__ char sm[];
    const uint32_t smem_u32 = (uint32_t)__cvta_generic_to_shared(sm);
    uint32_t* const ws  = reinterpret_cast<uint32_t*>(sm + WS_OFF);
    uint32_t* const wsi = reinterpret_cast<uint32_t*>(sm + WSI_OFF);

    const int tid  = threadIdx.x;
    const int wid  = tid >> 5;
    const int lane = tid & 31;
    const int bid  = blockIdx.x;
    const int jg    = bid >> 1;
    const int bhalf = bid & 1;
    const int j0    = jg * 16;
    const int row0  = bhalf * 64;
    const int mw    = wid >> 1;
    const int nh    = wid & 1;

    // ---- one-time: format Wh fragments (96KB) ----
    for (int idx = tid; idx < 24576; idx += 256) {
        const int r     = idx & 1;
        const int l     = (idx >> 1) & 31;
        const int rest  = idx >> 6;
        const int nhf   = rest & 1;
        const int rest2 = rest >> 1;
        const int tt    = rest2 % 3;
        const int ks    = rest2 / 3;
        const int n = tt * 1024 + j0 + nhf * 8 + (l >> 2);
        const int k = ks * 16 + r * 8 + (l & 3) * 2;
        const __half e0 = __float2half_rn(Wh[(size_t)k * 3072 + n]);
        const __half e1 = __float2half_rn(Wh[(size_t)(k + 1) * 3072 + n]);
        ws[idx] = ((uint32_t)__half_as_ushort(e1) << 16)
                |  (uint32_t)__half_as_ushort(e0);
    }
    // ---- one-time: format Wi fragments (48KB; same layout, K=512) ----
    for (int idx = tid; idx < 12288; idx += 256) {
        const int r     = idx & 1;
        const int l     = (idx >> 1) & 31;
        const int rest  = idx >> 6;
        const int nhf   = rest & 1;
        const int rest2 = rest >> 1;
        const int tt    = rest2 % 3;
        const int ksx   = rest2 / 3;       // 0..31
        const int n = tt * 1024 + j0 + nhf * 8 + (l >> 2);
        const int k = ksx * 16 + r * 8 + (l & 3) * 2;
        const __half e0 = __float2half_rn(Wi[(size_t)k * 3072 + n]);
        const __half e1 = __float2half_rn(Wi[(size_t)(k + 1) * 3072 + n]);
        wsi[idx] = ((uint32_t)__half_as_ushort(e1) << 16)
                 |  (uint32_t)__half_as_ushort(e0);
    }
    __syncthreads();

    const int b0r = row0 + mw * 16 + (lane >> 2);   // rows b0r, b0r+8
    const int jb  = j0 + nh * 8 + (lane & 3) * 2;   // cols jb, jb+1

    float biv[3][2], bhv[3][2];
#pragma unroll
    for (int g = 0; g < 3; g++) {
        biv[g][0] = bi[g * 1024 + jb];  biv[g][1] = bi[g * 1024 + jb + 1];
        bhv[g][0] = bh[g * 1024 + jb];  bhv[g][1] = bh[g * 1024 + jb + 1];
    }

    float hp[4];
#pragma unroll
    for (int p = 0; p < 4; p++) hp[p] = 0.f;

    const uint32_t apair = smem_u32 + A_OFF + mw * A_PAIR_SZ;
    const uint32_t xpair = smem_u32 + X_OFF + mw * X_PAIR_SZ;
    const int arow = row0 + mw * 16;
    const int baridx = 1 + mw;

    // thread-local ldmatrix base offsets
    const uint32_t a_ld = (uint32_t)((lane & 15) * 272 + (lane >> 4) * 16);
    const uint32_t x_ld = (uint32_t)((lane & 15) * 144 + (lane >> 4) * 16);

    // ================= pre-pass: xi_0 into xprev (x-only pipeline) ==========
    float xprev[3][4];
#pragma unroll
    for (int g = 0; g < 3; g++)
#pragma unroll
        for (int p = 0; p < 4; p++) xprev[g][p] = 0.f;

#pragma unroll
    for (int pc = 0; pc < 2; pc++) {
        const uint32_t xb = xpair + pc * X_BUF_SZ;
#pragma unroll
        for (int it = 0; it < 2; it++) {
            const int idx = nh * 64 + lane + it * 32;     // 0..127 over pair
            const int row = idx >> 3, off = idx & 7;
            cp16(xb + row * 144 + off * 16,
                 &g_xh[((size_t)(arow + row) * 512 + 0) * 512 + pc * 64 + off * 8]);
        }
        asm volatile("cp.async.commit_group;" ::: "memory");
    }
#pragma unroll 1
    for (int c = 0; c < 8; c++) {
        if (c < 7) asm volatile("cp.async.wait_group 1;" ::: "memory");
        else       asm volatile("cp.async.wait_group 0;" ::: "memory");
        asm volatile("bar.sync %0, 64;" :: "r"(baridx) : "memory");

        const uint32_t xbuf = xpair + (c % 3) * X_BUF_SZ;
#pragma unroll
        for (int kk = 0; kk < 4; kk++) {
            uint32_t xa[4];
            ldmatrix_x4(xa, xbuf + x_ld + kk * 32);
            const int ksx = c * 4 + kk;
#pragma unroll
            for (int tt = 0; tt < 3; tt++) {
                const uint32_t boff = smem_u32 + WSI_OFF
                    + (uint32_t)((((ksx * 3 + tt) * 2) + nh) * 256) + lane * 8;
                uint32_t w0, w1;
                asm("ld.shared.v2.u32 {%0,%1}, [%2];" : "=r"(w0), "=r"(w1) : "r"(boff));
                mma_f16(xprev[tt], xa, w0, w1);
            }
        }
        if (c < 6) {
            const uint32_t xb = xpair + ((c + 2) % 3) * X_BUF_SZ;
            const int kxb = (c + 2) * 64;
#pragma unroll
            for (int it = 0; it < 2; it++) {
                const int idx = nh * 64 + lane + it * 32;
                const int row = idx >> 3, off = idx & 7;
                cp16(xb + row * 144 + off * 16,
                     &g_xh[((size_t)(arow + row) * 512 + 0) * 512 + kxb + off * 8]);
            }
            asm volatile("cp.async.commit_group;" ::: "memory");
        }
    }

    // ================= main loop =============================================
#pragma unroll 1
    for (int t = 0; t < TSTEPS; t++) {
        const __half* __restrict__ hs = g_hf[t & 1];
        __half* __restrict__ hd = g_hf[(t + 1) & 1];
        const int tnext = (t < TSTEPS - 1) ? t + 1 : TSTEPS - 1;

        // prologue: stage chunks 0,1 of h AND x(t+1); one group per chunk
#pragma unroll
        for (int pc = 0; pc < 2; pc++) {
            const uint32_t ab = apair + pc * A_BUF_SZ;
#pragma unroll
            for (int it = 0; it < 4; it++) {
                const int idx = nh * 128 + lane + it * 32;   // 0..255 over pair
                const int row = idx >> 4, off = idx & 15;
                cp16(ab + row * 272 + off * 16,
                     &hs[(arow + row) * 1024 + pc * 128 + off * 8]);
            }
            const uint32_t xb = xpair + pc * X_BUF_SZ;
#pragma unroll
            for (int it = 0; it < 2; it++) {
                const int idx = nh * 64 + lane + it * 32;
                const int row = idx >> 3, off = idx & 7;
                cp16(xb + row * 144 + off * 16,
                     &g_xh[((size_t)(arow + row) * 512 + tnext) * 512 + pc * 64 + off * 8]);
            }
            asm volatile("cp.async.commit_group;" ::: "memory");
        }

        float acc[3][4], xacc[3][4];
#pragma unroll
        for (int g = 0; g < 3; g++)
#pragma unroll
            for (int p = 0; p < 4; p++) { acc[g][p] = 0.f; xacc[g][p] = 0.f; }

#pragma unroll 1
        for (int c = 0; c < 8; c++) {
            if (c < 7) asm volatile("cp.async.wait_group 1;" ::: "memory");
            else       asm volatile("cp.async.wait_group 0;" ::: "memory");
            asm volatile("bar.sync %0, 64;" :: "r"(baridx) : "memory");

            const uint32_t abuf = apair + (c % 3) * A_BUF_SZ;
            const uint32_t xbuf = xpair + (c % 3) * X_BUF_SZ;

            // h-recurrence mma: 8 kk x 3 gates
#pragma unroll
            for (int kk = 0; kk < 8; kk++) {
                uint32_t a[4];
                ldmatrix_x4(a, abuf + a_ld + kk * 32);
                const int ks = c * 8 + kk;
#pragma unroll
                for (int tt = 0; tt < 3; tt++) {
                    const uint32_t boff = smem_u32 + WS_OFF
                        + (uint32_t)((((ks * 3 + tt) * 2) + nh) * 256) + lane * 8;
                    uint32_t w0, w1;
                    asm("ld.shared.v2.u32 {%0,%1}, [%2];" : "=r"(w0), "=r"(w1) : "r"(boff));
                    mma_f16(acc[tt], a, w0, w1);
                }
            }
            // xi(t+1) mma: 4 kk x 3 gates
#pragma unroll
            for (int kk = 0; kk < 4; kk++) {
                uint32_t xa[4];
                ldmatrix_x4(xa, xbuf + x_ld + kk * 32);
                const int ksx = c * 4 + kk;
#pragma unroll
                for (int tt = 0; tt < 3; tt++) {
                    const uint32_t boff = smem_u32 + WSI_OFF
                        + (uint32_t)((((ksx * 3 + tt) * 2) + nh) * 256) + lane * 8;
                    uint32_t w0, w1;
                    asm("ld.shared.v2.u32 {%0,%1}, [%2];" : "=r"(w0), "=r"(w1) : "r"(boff));
                    mma_f16(xacc[tt], xa, w0, w1);
                }
            }

            if (c < 6) {   // stage chunk c+2 (h and x), one group
                const uint32_t ab = apair + ((c + 2) % 3) * A_BUF_SZ;
                const int kb = (c + 2) * 128;
#pragma unroll
                for (int it = 0; it < 4; it++) {
                    const int idx = nh * 128 + lane + it * 32;
                    const int row = idx >> 4, off = idx & 15;
                    cp16(ab + row * 272 + off * 16,
                         &hs[(arow + row) * 1024 + kb + off * 8]);
                }
                const uint32_t xb = xpair + ((c + 2) % 3) * X_BUF_SZ;
                const int kxb = (c + 2) * 64;
#pragma unroll
                for (int it = 0; it < 2; it++) {
                    const int idx = nh * 64 + lane + it * 32;
                    const int row = idx >> 3, off = idx & 7;
                    cp16(xb + row * 144 + off * 16,
                         &g_xh[((size_t)(arow + row) * 512 + tnext) * 512 + kxb + off * 8]);
                }
                asm volatile("cp.async.commit_group;" ::: "memory");
            }
        }

        // ---------------- gate epilogue (all registers) ----------------
#pragma unroll
        for (int rr = 0; rr < 2; rr++) {
            const int b = b0r + rr * 8;
            float hy2[2];
#pragma unroll
            for (int q = 0; q < 2; q++) {
                const int p = rr * 2 + q;
                const float rg = fsigmoid((xprev[0][p] + biv[0][q])
                                        + (acc[0][p] + bhv[0][q]));
                const float zg = fsigmoid((xprev[1][p] + biv[1][q])
                                        + (acc[1][p] + bhv[1][q]));
                const float ng = ftanh_((xprev[2][p] + biv[2][q])
                                      + rg * (acc[2][p] + bhv[2][q]));
                const float hy = zg * ng + (1.f - zg) * hp[p];
                hp[p] = hy;
                hy2[q] = hy;
            }
            const __half e0 = __float2half_rn(hy2[0]);
            const __half e1 = __float2half_rn(hy2[1]);
            *reinterpret_cast<uint32_t*>(&hd[b * 1024 + jb]) =
                ((uint32_t)__half_as_ushort(e1) << 16)
                | (uint32_t)__half_as_ushort(e0);
            if (t == TSTEPS - 1) {
                float2 o; o.x = hy2[0]; o.y = hy2[1];
                *reinterpret_cast<float2*>(&out[b * 1024 + jb]) = o;
            }
        }

        // rotate xi registers: xprev <- xacc (xi for step t+1)
#pragma unroll
        for (int g = 0; g < 3; g++)
#pragma unroll
            for (int p = 0; p < 4; p++) xprev[g][p] = xacc[g][p];

        if (t != TSTEPS - 1) grid_barrier_step((unsigned)(t + 1) * NC);
    }
}

// ---------------- launch ----------------------------------------------------
extern "C" void kernel_launch(void* const* d_in, const int* in_sizes, int n_in,
                              void* d_out, int out_size)
{
    const float* x  = (const float*)d_in[0];
    const float* Wi = (const float*)d_in[1];
    const float* bi = (const float*)d_in[2];
    const float* Wh = (const float*)d_in[3];
    const float* bh = (const float*)d_in[4];
    float* out = (float*)d_out;

    cudaFuncSetAttribute(gru_fused_persist,
                         cudaFuncAttributeMaxDynamicSharedMemorySize, SMEM_TOTAL);

    // prep: x -> fp16
    split_x<<<131072, 256>>>(x);
    // zero h buffer + barrier counter
    init_state<<<512, 256>>>();
    // fused: xi production (1 step ahead, in registers) + 512-step recurrence
    gru_fused_persist<<<NC, 256, SMEM_TOTAL>>>(Wh, Wi, bi, bh, out);
}